// round 1
// baseline (speedup 1.0000x reference)
#include <cuda_runtime.h>
#include <math.h>

#define HH 512
#define WW 512
#define NVIEW 768
#define NDCT 736
#define NT 725

// Channel-interleaved image: g_img[y*W+x] = (ch0, ch1). 2 MB static scratch.
__device__ float2 g_img[HH * WW];

__global__ void interleave_kernel(const float* __restrict__ in) {
    int i = blockIdx.x * blockDim.x + threadIdx.x;
    if (i < HH * WW) {
        g_img[i] = make_float2(in[i], in[HH * WW + i]);
    }
}

// Compute clipped t-range [k0, k1] (k = t + 362) for ray:
//   x(t) = bx - sn*t,  y(t) = by + c*t,  valid region x,y in (-1, 512)
__device__ __forceinline__ void clip_ray(float bx, float by, float sn, float c,
                                         int& k0, int& k1) {
    float tlo = -362.0f, thi = 362.0f;
    const float lo = -1.01f;
    const float hi = 512.01f;
    // x = bx - sn*t ; sn >= 0 always (theta in [0, pi))
    if (sn > 1e-7f) {
        float inv = __frcp_rn(sn);
        tlo = fmaxf(tlo, (bx - hi) * inv);
        thi = fminf(thi, (bx - lo) * inv);
    } else if (bx <= lo || bx >= hi) {
        thi = tlo - 1.0f;
    }
    // y = by + c*t
    if (c > 1e-7f) {
        float inv = __frcp_rn(c);
        tlo = fmaxf(tlo, (lo - by) * inv);
        thi = fminf(thi, (hi - by) * inv);
    } else if (c < -1e-7f) {
        float inv = __frcp_rn(c);
        tlo = fmaxf(tlo, (hi - by) * inv);
        thi = fminf(thi, (lo - by) * inv);
    } else if (by <= lo || by >= hi) {
        thi = tlo - 1.0f;
    }
    k0 = max(0, (int)ceilf(tlo + 362.0f));
    k1 = min(NT - 1, (int)floorf(thi + 362.0f));
}

// Safe bilinear sample of g_img at (x, y) with zero padding, accumulate both channels.
__device__ __forceinline__ void sample_acc(float x, float y, float& accx, float& accy) {
    int ix = __float2int_rd(x);
    int iy = __float2int_rd(y);
    float wx = x - (float)ix;
    float wy = y - (float)iy;
    bool vx0 = ((unsigned)ix < (unsigned)WW);
    bool vx1 = ((unsigned)(ix + 1) < (unsigned)WW);
    bool vy0 = ((unsigned)iy < (unsigned)HH);
    bool vy1 = ((unsigned)(iy + 1) < (unsigned)HH);
    int cx0 = min(max(ix, 0), WW - 1);
    int cx1 = min(max(ix + 1, 0), WW - 1);
    int cy0 = min(max(iy, 0), HH - 1);
    int cy1 = min(max(iy + 1, 0), HH - 1);
    int r0 = cy0 * WW;
    int r1 = cy1 * WW;
    float2 v00 = g_img[r0 + cx0];
    float2 v01 = g_img[r0 + cx1];
    float2 v10 = g_img[r1 + cx0];
    float2 v11 = g_img[r1 + cx1];
    float wx0 = 1.0f - wx;
    float wy0 = 1.0f - wy;
    float w00 = (vx0 && vy0) ? wx0 * wy0 : 0.0f;
    float w01 = (vx1 && vy0) ? wx * wy0 : 0.0f;
    float w10 = (vx0 && vy1) ? wx0 * wy : 0.0f;
    float w11 = (vx1 && vy1) ? wx * wy : 0.0f;
    accx = fmaf(w00, v00.x, accx);
    accx = fmaf(w01, v01.x, accx);
    accx = fmaf(w10, v10.x, accx);
    accx = fmaf(w11, v11.x, accx);
    accy = fmaf(w00, v00.y, accy);
    accy = fmaf(w01, v01.y, accy);
    accy = fmaf(w10, v10.y, accy);
    accy = fmaf(w11, v11.y, accy);
}

// Kernel A: views with |cos| >= sin (theta in [0,pi/4] U [3pi/4,pi)).
// Lanes map to adjacent s (delta-y per lane = sin(theta) <= 0.707); each
// thread owns one (view, s) and loops over the clipped t range.
__global__ void __launch_bounds__(256) radonA(float* __restrict__ out) {
    int s = blockIdx.x * blockDim.x + threadIdx.x;
    int vy = blockIdx.y;
    int v = (vy < 193) ? vy : (vy + 383);
    if (s >= NDCT) return;

    float theta = (float)v * (float)(M_PI / (double)NVIEW);
    float sn, c;
    sincosf(theta, &sn, &c);
    float sf = (float)s - 367.5f;
    float bx = fmaf(sf, c, 255.5f);
    float by = fmaf(sf, sn, 255.5f);

    int k0, k1;
    clip_ray(bx, by, sn, c, k0, k1);

    float accx = 0.0f, accy = 0.0f;
    #pragma unroll 2
    for (int k = k0; k <= k1; ++k) {
        float t = (float)k - 362.0f;
        float x = fmaf(t, -sn, bx);
        float y = fmaf(t, c, by);
        sample_acc(x, y, accx, accy);
    }
    out[v * NDCT + s] = accx;
    out[NVIEW * NDCT + v * NDCT + s] = accy;
}

// Kernel B: views with sin > |cos| (theta in (pi/4, 3pi/4)).
// One warp per (view, s); lanes stride over t (delta-y per lane = |cos| <= 0.707),
// warp butterfly reduction at the end.
__global__ void __launch_bounds__(256) radonB(float* __restrict__ out) {
    int warp = threadIdx.x >> 5;
    int lane = threadIdx.x & 31;
    int s = blockIdx.x * 8 + warp;
    int v = 193 + blockIdx.y;
    if (s >= NDCT) return;

    float theta = (float)v * (float)(M_PI / (double)NVIEW);
    float sn, c;
    sincosf(theta, &sn, &c);
    float sf = (float)s - 367.5f;
    float bx = fmaf(sf, c, 255.5f);
    float by = fmaf(sf, sn, 255.5f);

    int k0, k1;
    clip_ray(bx, by, sn, c, k0, k1);

    float accx = 0.0f, accy = 0.0f;
    for (int k = k0 + lane; k <= k1; k += 32) {
        float t = (float)k - 362.0f;
        float x = fmaf(t, -sn, bx);
        float y = fmaf(t, c, by);
        sample_acc(x, y, accx, accy);
    }
    #pragma unroll
    for (int off = 16; off > 0; off >>= 1) {
        accx += __shfl_xor_sync(0xFFFFFFFFu, accx, off);
        accy += __shfl_xor_sync(0xFFFFFFFFu, accy, off);
    }
    if (lane == 0) {
        out[v * NDCT + s] = accx;
        out[NVIEW * NDCT + v * NDCT + s] = accy;
    }
}

extern "C" void kernel_launch(void* const* d_in, const int* in_sizes, int n_in,
                              void* d_out, int out_size) {
    const float* in = (const float*)d_in[0];
    float* out = (float*)d_out;

    interleave_kernel<<<(HH * WW + 255) / 256, 256>>>(in);

    // Kernel A: 385 views (v in [0,192] U [576,767]), 736 detectors.
    dim3 gridA((NDCT + 255) / 256, 385);
    radonA<<<gridA, 256>>>(out);

    // Kernel B: 383 views (v in [193,575]), one warp per detector.
    dim3 gridB(NDCT / 8, 383);
    radonB<<<gridB, 256>>>(out);
}

// round 2
// speedup vs baseline: 1.4411x; 1.4411x over previous
#include <cuda_runtime.h>
#include <math.h>

#define HH 512
#define WW 512
#define NVIEW 768
#define NDCT 736
#define NT 725

// Padded pair table: g_pair[py*PW+px] = (c0[y][x-1], c1[y][x-1], c0[y][x], c1[y][x])
// with y = py-1, x = px. One-entry zero border on all sides (weights never need
// masking: out-of-image taps read stored zeros).
#define PW 513
#define PH 514
__device__ float4 g_pair[PH * PW];

__global__ void build_pair(const float* __restrict__ in) {
    int i = blockIdx.x * blockDim.x + threadIdx.x;
    if (i >= PH * PW) return;
    int py = i / PW;
    int px = i - py * PW;
    int y = py - 1;
    int x0 = px - 1;
    float4 v = make_float4(0.0f, 0.0f, 0.0f, 0.0f);
    if (y >= 0 && y < HH) {
        if (x0 >= 0) {
            v.x = in[y * WW + x0];
            v.y = in[HH * WW + y * WW + x0];
        }
        if (px < WW) {
            v.z = in[y * WW + px];
            v.w = in[HH * WW + y * WW + px];
        }
    }
    g_pair[i] = v;
}

// Clip t so that x(t)=bx-sn*t and y(t)=by+c*t stay inside (-0.999, 511.999).
// This guarantees ix in [-1,511], iy in [-1,511] -> padded indices always valid.
__device__ __forceinline__ void clip_ray(float bx, float by, float sn, float c,
                                         int& k0, int& k1) {
    float tlo = -362.0f, thi = 362.0f;
    const float lo = -0.999f;
    const float hi = 511.999f;
    // x = bx - sn*t ; sn >= 0 for theta in [0, pi)
    if (sn > 1e-7f) {
        float inv = __frcp_rn(sn);
        tlo = fmaxf(tlo, (bx - hi) * inv);
        thi = fminf(thi, (bx - lo) * inv);
    } else if (bx <= lo || bx >= hi) {
        thi = tlo - 1.0f;
    }
    // y = by + c*t
    if (c > 1e-7f) {
        float inv = __frcp_rn(c);
        tlo = fmaxf(tlo, (lo - by) * inv);
        thi = fminf(thi, (hi - by) * inv);
    } else if (c < -1e-7f) {
        float inv = __frcp_rn(c);
        tlo = fmaxf(tlo, (hi - by) * inv);
        thi = fminf(thi, (lo - by) * inv);
    } else if (by <= lo || by >= hi) {
        thi = tlo - 1.0f;
    }
    k0 = max(0, (int)ceilf(tlo + 362.0f));
    k1 = min(NT - 1, (int)floorf(thi + 362.0f));
}

// Branchless bilinear sample + accumulate (both channels). 2x LDG.128.
__device__ __forceinline__ void sample_acc(float x, float y, float& accx, float& accy) {
    float fx = floorf(x);
    float fy = floorf(y);
    int ix = (int)fx;
    int iy = (int)fy;
    float wx = x - fx;
    float wy = y - fy;
    int base = (iy + 1) * PW + (ix + 1);
    float4 r0 = g_pair[base];
    float4 r1 = g_pair[base + PW];
    float wx0 = 1.0f - wx;
    float wy0 = 1.0f - wy;
    float a0 = fmaf(wx0, r0.x, wx * r0.z);  // row0 ch0
    float b0 = fmaf(wx0, r0.y, wx * r0.w);  // row0 ch1
    float a1 = fmaf(wx0, r1.x, wx * r1.z);  // row1 ch0
    float b1 = fmaf(wx0, r1.y, wx * r1.w);  // row1 ch1
    accx = fmaf(wy0, a0, accx);
    accx = fmaf(wy, a1, accx);
    accy = fmaf(wy0, b0, accy);
    accy = fmaf(wy, b1, accy);
}

// Kernel A: views with |cos| >= sin (v in [0,192] U [576,767]).
// Lanes along s (delta-y per lane = sin <= 0.707); thread owns one (view,s).
__global__ void __launch_bounds__(256) radonA(float* __restrict__ out) {
    int s = blockIdx.x * blockDim.x + threadIdx.x;
    int vy = blockIdx.y;
    int v = (vy < 193) ? vy : (vy + 383);
    if (s >= NDCT) return;

    float theta = (float)v * (float)(M_PI / (double)NVIEW);
    float sn, c;
    sincosf(theta, &sn, &c);
    float sf = (float)s - 367.5f;
    float bx = fmaf(sf, c, 255.5f);
    float by = fmaf(sf, sn, 255.5f);

    int k0, k1;
    clip_ray(bx, by, sn, c, k0, k1);

    float accx = 0.0f, accy = 0.0f;
    #pragma unroll 4
    for (int k = k0; k <= k1; ++k) {
        float t = (float)k - 362.0f;
        float x = fmaf(t, -sn, bx);
        float y = fmaf(t, c, by);
        sample_acc(x, y, accx, accy);
    }
    out[v * NDCT + s] = accx;
    out[NVIEW * NDCT + v * NDCT + s] = accy;
}

// Kernel B: views with sin > |cos| (v in [193,575]).
// One warp per (view,s); lanes stride over t (delta-y per lane = |cos| <= 0.707).
__global__ void __launch_bounds__(256) radonB(float* __restrict__ out) {
    int warp = threadIdx.x >> 5;
    int lane = threadIdx.x & 31;
    int s = blockIdx.x * 8 + warp;
    int v = 193 + blockIdx.y;
    if (s >= NDCT) return;

    float theta = (float)v * (float)(M_PI / (double)NVIEW);
    float sn, c;
    sincosf(theta, &sn, &c);
    float sf = (float)s - 367.5f;
    float bx = fmaf(sf, c, 255.5f);
    float by = fmaf(sf, sn, 255.5f);

    int k0, k1;
    clip_ray(bx, by, sn, c, k0, k1);

    float accx = 0.0f, accy = 0.0f;
    #pragma unroll 2
    for (int k = k0 + lane; k <= k1; k += 32) {
        float t = (float)k - 362.0f;
        float x = fmaf(t, -sn, bx);
        float y = fmaf(t, c, by);
        sample_acc(x, y, accx, accy);
    }
    #pragma unroll
    for (int off = 16; off > 0; off >>= 1) {
        accx += __shfl_xor_sync(0xFFFFFFFFu, accx, off);
        accy += __shfl_xor_sync(0xFFFFFFFFu, accy, off);
    }
    if (lane == 0) {
        out[v * NDCT + s] = accx;
        out[NVIEW * NDCT + v * NDCT + s] = accy;
    }
}

extern "C" void kernel_launch(void* const* d_in, const int* in_sizes, int n_in,
                              void* d_out, int out_size) {
    const float* in = (const float*)d_in[0];
    float* out = (float*)d_out;

    build_pair<<<(PH * PW + 255) / 256, 256>>>(in);

    dim3 gridA((NDCT + 255) / 256, 385);
    radonA<<<gridA, 256>>>(out);

    dim3 gridB(NDCT / 8, 383);
    radonB<<<gridB, 256>>>(out);
}

// round 3
// speedup vs baseline: 1.4778x; 1.0255x over previous
#include <cuda_runtime.h>
#include <math.h>

#define HH 512
#define WW 512
#define NVIEW 768
#define NDCT 736
#define NT 725

// Padded pair table: g_pair[py*PW+px] = (c0[y][x-1], c1[y][x-1], c0[y][x], c1[y][x])
// with y = py-1, x = px. One-entry zero border on all sides.
#define PW 513
#define PH 514
__device__ float4 g_pair[PH * PW];

__global__ void build_pair(const float* __restrict__ in) {
    int i = blockIdx.x * blockDim.x + threadIdx.x;
    if (i >= PH * PW) return;
    int py = i / PW;
    int px = i - py * PW;
    int y = py - 1;
    int x0 = px - 1;
    float4 v = make_float4(0.0f, 0.0f, 0.0f, 0.0f);
    if (y >= 0 && y < HH) {
        if (x0 >= 0) {
            v.x = in[y * WW + x0];
            v.y = in[HH * WW + y * WW + x0];
        }
        if (px < WW) {
            v.z = in[y * WW + px];
            v.w = in[HH * WW + y * WW + px];
        }
    }
    g_pair[i] = v;
}

// Clip t so x(t)=bx-sn*t, y(t)=by+c*t stay inside (-0.999, 511.999):
// guarantees padded indices valid and out-of-image taps hit stored zeros.
__device__ __forceinline__ void clip_ray(float bx, float by, float sn, float c,
                                         int& k0, int& k1) {
    float tlo = -362.0f, thi = 362.0f;
    const float lo = -0.999f;
    const float hi = 511.999f;
    if (sn > 1e-7f) {
        float inv = __frcp_rn(sn);
        tlo = fmaxf(tlo, (bx - hi) * inv);
        thi = fminf(thi, (bx - lo) * inv);
    } else if (bx <= lo || bx >= hi) {
        thi = tlo - 1.0f;
    }
    if (c > 1e-7f) {
        float inv = __frcp_rn(c);
        tlo = fmaxf(tlo, (lo - by) * inv);
        thi = fminf(thi, (hi - by) * inv);
    } else if (c < -1e-7f) {
        float inv = __frcp_rn(c);
        tlo = fmaxf(tlo, (hi - by) * inv);
        thi = fminf(thi, (lo - by) * inv);
    } else if (by <= lo || by >= hi) {
        thi = tlo - 1.0f;
    }
    k0 = max(0, (int)ceilf(tlo + 362.0f));
    k1 = min(NT - 1, (int)floorf(thi + 362.0f));
}

// Branchless bilinear sample + accumulate both channels. 2x LDG.128.
__device__ __forceinline__ void sample_acc(float x, float y, float& accx, float& accy) {
    float fx = floorf(x);
    float fy = floorf(y);
    int ix = (int)fx;
    int iy = (int)fy;
    float wx = x - fx;
    float wy = y - fy;
    int base = (iy + 1) * PW + (ix + 1);
    float4 r0 = g_pair[base];
    float4 r1 = g_pair[base + PW];
    float wx0 = 1.0f - wx;
    float wy0 = 1.0f - wy;
    float a0 = fmaf(wx0, r0.x, wx * r0.z);
    float b0 = fmaf(wx0, r0.y, wx * r0.w);
    float a1 = fmaf(wx0, r1.x, wx * r1.z);
    float b1 = fmaf(wx0, r1.y, wx * r1.w);
    accx = fmaf(wy0, a0, accx);
    accx = fmaf(wy, a1, accx);
    accy = fmaf(wy0, b0, accy);
    accy = fmaf(wy, b1, accy);
}

__device__ __forceinline__ void ray_setup(int v, int s, float& sn, float& c,
                                          float& bx, float& by, int& k0, int& k1) {
    float theta = (float)v * (float)(M_PI / (double)NVIEW);
    sincosf(theta, &sn, &c);
    float sf = (float)s - 367.5f;
    bx = fmaf(sf, c, 255.5f);
    by = fmaf(sf, sn, 255.5f);
    clip_ray(bx, by, sn, c, k0, k1);
}

// Kernel A: views with |cos| >= sin (v in [0,192] U [576,767]).
// Warp tile: 8 detectors (si = lane&7) x 4 t-offsets (ti = lane>>3).
// Warp y-footprint = 8*sin + 4*|cos| <= 8.5 rows.
__global__ void __launch_bounds__(256) radonA(float* __restrict__ out) {
    int lane = threadIdx.x & 31;
    int warp = threadIdx.x >> 5;
    int si = lane & 7;
    int ti = lane >> 3;           // 0..3
    int s = blockIdx.x * 64 + warp * 8 + si;
    int vy = blockIdx.y;
    int v = (vy < 193) ? vy : (vy + 383);
    if (s >= NDCT) return;        // whole warp uniform (8 | NDCT)

    float sn, c, bx, by;
    int k0, k1;
    ray_setup(v, s, sn, c, bx, by, k0, k1);

    float accx = 0.0f, accy = 0.0f;
    #pragma unroll 2
    for (int k = k0 + ti; k <= k1; k += 4) {
        float t = (float)k - 362.0f;
        float x = fmaf(t, -sn, bx);
        float y = fmaf(t, c, by);
        sample_acc(x, y, accx, accy);
    }
    // reduce over ti groups (lanes differing in bits 3,4)
    accx += __shfl_xor_sync(0xFFFFFFFFu, accx, 8);
    accy += __shfl_xor_sync(0xFFFFFFFFu, accy, 8);
    accx += __shfl_xor_sync(0xFFFFFFFFu, accx, 16);
    accy += __shfl_xor_sync(0xFFFFFFFFu, accy, 16);
    if (lane < 8) {
        out[v * NDCT + s] = accx;
        out[NVIEW * NDCT + v * NDCT + s] = accy;
    }
}

// Kernel B: views with sin > |cos| (v in [193,575]).
// Warp tile: 4 detectors (si = lane&3) x 8 t-strides (ti = lane>>2).
// Warp y-footprint = 8*|cos| + 4*sin <= 8.5 rows.
__global__ void __launch_bounds__(256) radonB(float* __restrict__ out) {
    int lane = threadIdx.x & 31;
    int warp = threadIdx.x >> 5;
    int si = lane & 3;
    int ti = lane >> 2;           // 0..7
    int s = blockIdx.x * 32 + warp * 4 + si;
    int v = 193 + blockIdx.y;

    float sn, c, bx, by;
    int k0, k1;
    ray_setup(v, s, sn, c, bx, by, k0, k1);

    float accx = 0.0f, accy = 0.0f;
    #pragma unroll 2
    for (int k = k0 + ti; k <= k1; k += 8) {
        float t = (float)k - 362.0f;
        float x = fmaf(t, -sn, bx);
        float y = fmaf(t, c, by);
        sample_acc(x, y, accx, accy);
    }
    // reduce over ti groups (lanes differing in bits 2,3,4)
    accx += __shfl_xor_sync(0xFFFFFFFFu, accx, 4);
    accy += __shfl_xor_sync(0xFFFFFFFFu, accy, 4);
    accx += __shfl_xor_sync(0xFFFFFFFFu, accx, 8);
    accy += __shfl_xor_sync(0xFFFFFFFFu, accy, 8);
    accx += __shfl_xor_sync(0xFFFFFFFFu, accx, 16);
    accy += __shfl_xor_sync(0xFFFFFFFFu, accy, 16);
    if (lane < 4) {
        out[v * NDCT + s] = accx;
        out[NVIEW * NDCT + v * NDCT + s] = accy;
    }
}

extern "C" void kernel_launch(void* const* d_in, const int* in_sizes, int n_in,
                              void* d_out, int out_size) {
    const float* in = (const float*)d_in[0];
    float* out = (float*)d_out;

    build_pair<<<(PH * PW + 255) / 256, 256>>>(in);

    // Kernel A: 385 views, 64 detectors per block (8 warps x 8 det).
    dim3 gridA((NDCT + 63) / 64, 385);
    radonA<<<gridA, 256>>>(out);

    // Kernel B: 383 views, 32 detectors per block (8 warps x 4 det). 736 = 23*32.
    dim3 gridB(NDCT / 32, 383);
    radonB<<<gridB, 256>>>(out);
}

// round 4
// speedup vs baseline: 1.5415x; 1.0431x over previous
#include <cuda_runtime.h>
#include <math.h>

#define HH 512
#define WW 512
#define NVIEW 768
#define NDCT 736
#define NT 725

// Padded pair table: g_pair[py*PW+px] = (c0[y][x-1], c1[y][x-1], c0[y][x], c1[y][x])
// with y = py-1, x = px-? : entry px covers image columns px-1 and px; zero border.
#define PW 513
#define PH 514
__device__ float4 g_pair[PH * PW];

__global__ void build_pair(const float* __restrict__ in) {
    int i = blockIdx.x * blockDim.x + threadIdx.x;
    if (i >= PH * PW) return;
    int py = i / PW;
    int px = i - py * PW;
    int y = py - 1;
    int x0 = px - 1;
    float4 v = make_float4(0.0f, 0.0f, 0.0f, 0.0f);
    if (y >= 0 && y < HH) {
        if (x0 >= 0) {
            v.x = in[y * WW + x0];
            v.y = in[HH * WW + y * WW + x0];
        }
        if (px < WW) {
            v.z = in[y * WW + px];
            v.w = in[HH * WW + y * WW + px];
        }
    }
    g_pair[i] = v;
}

// Clip t so x(t)=bx-sn*t, y(t)=by+c*t stay inside (-0.999, 511.999).
__device__ __forceinline__ void clip_ray(float bx, float by, float sn, float c,
                                         int& k0, int& k1) {
    float tlo = -362.0f, thi = 362.0f;
    const float lo = -0.999f;
    const float hi = 511.999f;
    if (sn > 1e-7f) {
        float inv = __frcp_rn(sn);
        tlo = fmaxf(tlo, (bx - hi) * inv);
        thi = fminf(thi, (bx - lo) * inv);
    } else if (bx <= lo || bx >= hi) {
        thi = tlo - 1.0f;
    }
    if (c > 1e-7f) {
        float inv = __frcp_rn(c);
        tlo = fmaxf(tlo, (lo - by) * inv);
        thi = fminf(thi, (hi - by) * inv);
    } else if (c < -1e-7f) {
        float inv = __frcp_rn(c);
        tlo = fmaxf(tlo, (hi - by) * inv);
        thi = fminf(thi, (lo - by) * inv);
    } else if (by <= lo || by >= hi) {
        thi = tlo - 1.0f;
    }
    k0 = max(0, (int)ceilf(tlo + 362.0f));
    k1 = min(NT - 1, (int)floorf(thi + 362.0f));
}

#define MAGIC 8388608.0f  // 2^23

#define FFMA2(d, a, b, c) \
    asm("fma.rn.f32x2 %0, %1, %2, %3;" : "=l"(d) : "l"(a), "l"(b), "l"(c))
#define FMUL2(d, a, b) \
    asm("mul.rn.f32x2 %0, %1, %2;" : "=l"(d) : "l"(a), "l"(b))
#define FPACK(d, lo, hi) \
    asm("mov.b64 %0, {%1, %2};" : "=l"(d) : "f"(lo), "f"(hi))
#define FUNPACK(lo, hi, s) \
    asm("mov.b64 {%0, %1}, %2;" : "=f"(lo), "=f"(hi) : "l"(s))

// Branchless, conversion-free bilinear sample in padded coords (xp,yp in (0,513)).
// Accumulates both channels into two packed f32x2 accumulators.
__device__ __forceinline__ void sample_acc(float xp, float yp,
                                           unsigned long long& accA,
                                           unsigned long long& accB) {
    float sx = __fadd_rd(xp, MAGIC);
    float sy = __fadd_rd(yp, MAGIC);
    int ixp = __float_as_int(sx) & 0x7FFFFF;
    int iyp = __float_as_int(sy) & 0x7FFFFF;
    float wx = xp - (sx - MAGIC);
    float wy = yp - (sy - MAGIC);
    float wx0 = 1.0f - wx;
    float wy0 = 1.0f - wy;

    int base = iyp * PW + ixp;
    const ulonglong2* p = (const ulonglong2*)g_pair;
    ulonglong2 r0 = p[base];        // (ch-pair at x0, ch-pair at x0+1), row iy
    ulonglong2 r1 = p[base + PW];   // row iy+1

    unsigned long long wxd, wx0d, wyd, wy0d;
    FPACK(wx0d, wx0, wx0);
    FPACK(wxd, wx, wx);
    FPACK(wy0d, wy0, wy0);
    FPACK(wyd, wy, wy);

    unsigned long long a0, a1, t0, t1;
    FMUL2(t0, wx0d, r0.x);
    FFMA2(a0, wxd, r0.y, t0);       // x-lerped row0 (both channels)
    FMUL2(t1, wx0d, r1.x);
    FFMA2(a1, wxd, r1.y, t1);       // x-lerped row1
    FFMA2(accA, wy0d, a0, accA);
    FFMA2(accB, wyd, a1, accB);
}

__device__ __forceinline__ void ray_setup(int v, int s, float& sn, float& c,
                                          float& bxp, float& byp, int& k0, int& k1) {
    float theta = (float)v * (float)(M_PI / (double)NVIEW);
    sincosf(theta, &sn, &c);
    float sf = (float)s - 367.5f;
    float bx = fmaf(sf, c, 255.5f);
    float by = fmaf(sf, sn, 255.5f);
    clip_ray(bx, by, sn, c, k0, k1);
    bxp = bx + 1.0f;   // padded coords
    byp = by + 1.0f;
}

// Kernel A: views with |cos| >= sin (v in [0,192] U [576,767]).
// Warp tile: 8 detectors x 4 t-offsets.
__global__ void __launch_bounds__(256) radonA(float* __restrict__ out) {
    int lane = threadIdx.x & 31;
    int warp = threadIdx.x >> 5;
    int si = lane & 7;
    int ti = lane >> 3;           // 0..3
    int s = blockIdx.x * 64 + warp * 8 + si;
    int vy = blockIdx.y;
    int v = (vy < 193) ? vy : (vy + 383);
    if (s >= NDCT) return;        // warp-uniform

    float sn, c, bxp, byp;
    int k0, k1;
    ray_setup(v, s, sn, c, bxp, byp, k0, k1);

    unsigned long long accA = 0ULL, accB = 0ULL;
    float tf = (float)(k0 + ti) - 362.0f;
    #pragma unroll 2
    for (int k = k0 + ti; k <= k1; k += 4) {
        float xp = fmaf(tf, -sn, bxp);
        float yp = fmaf(tf, c, byp);
        sample_acc(xp, yp, accA, accB);
        tf += 4.0f;
    }
    float ax, ay, bx2, by2;
    FUNPACK(ax, ay, accA);
    FUNPACK(bx2, by2, accB);
    float accx = ax + bx2;
    float accy = ay + by2;
    accx += __shfl_xor_sync(0xFFFFFFFFu, accx, 8);
    accy += __shfl_xor_sync(0xFFFFFFFFu, accy, 8);
    accx += __shfl_xor_sync(0xFFFFFFFFu, accx, 16);
    accy += __shfl_xor_sync(0xFFFFFFFFu, accy, 16);
    if (lane < 8) {
        out[v * NDCT + s] = accx;
        out[NVIEW * NDCT + v * NDCT + s] = accy;
    }
}

// Kernel B: views with sin > |cos| (v in [193,575]).
// Warp tile: 4 detectors x 8 t-strides.
__global__ void __launch_bounds__(256) radonB(float* __restrict__ out) {
    int lane = threadIdx.x & 31;
    int warp = threadIdx.x >> 5;
    int si = lane & 3;
    int ti = lane >> 2;           // 0..7
    int s = blockIdx.x * 32 + warp * 4 + si;
    int v = 193 + blockIdx.y;

    float sn, c, bxp, byp;
    int k0, k1;
    ray_setup(v, s, sn, c, bxp, byp, k0, k1);

    unsigned long long accA = 0ULL, accB = 0ULL;
    float tf = (float)(k0 + ti) - 362.0f;
    #pragma unroll 2
    for (int k = k0 + ti; k <= k1; k += 8) {
        float xp = fmaf(tf, -sn, bxp);
        float yp = fmaf(tf, c, byp);
        sample_acc(xp, yp, accA, accB);
        tf += 8.0f;
    }
    float ax, ay, bx2, by2;
    FUNPACK(ax, ay, accA);
    FUNPACK(bx2, by2, accB);
    float accx = ax + bx2;
    float accy = ay + by2;
    accx += __shfl_xor_sync(0xFFFFFFFFu, accx, 4);
    accy += __shfl_xor_sync(0xFFFFFFFFu, accy, 4);
    accx += __shfl_xor_sync(0xFFFFFFFFu, accx, 8);
    accy += __shfl_xor_sync(0xFFFFFFFFu, accy, 8);
    accx += __shfl_xor_sync(0xFFFFFFFFu, accx, 16);
    accy += __shfl_xor_sync(0xFFFFFFFFu, accy, 16);
    if (lane < 4) {
        out[v * NDCT + s] = accx;
        out[NVIEW * NDCT + v * NDCT + s] = accy;
    }
}

extern "C" void kernel_launch(void* const* d_in, const int* in_sizes, int n_in,
                              void* d_out, int out_size) {
    const float* in = (const float*)d_in[0];
    float* out = (float*)d_out;

    build_pair<<<(PH * PW + 255) / 256, 256>>>(in);

    dim3 gridA((NDCT + 63) / 64, 385);
    radonA<<<gridA, 256>>>(out);

    dim3 gridB(NDCT / 32, 383);
    radonB<<<gridB, 256>>>(out);
}

// round 5
// speedup vs baseline: 2.3234x; 1.5072x over previous
#include <cuda_runtime.h>
#include <cuda_fp16.h>
#include <math.h>

#define HH 512
#define WW 512
#define NVIEW 768
#define NDCT 736
#define NT 725

#define PW 513
#define PH 514

// fp16 pair table: g_ph[py*PW+px] = { half2(c0,c1)@x=px-1, half2(c0,c1)@x=px },
// image row y = py-1, one-entry zero border on all sides. 8 bytes per entry.
struct __align__(8) HPair { __half2 lo, hi; };
__device__ HPair g_ph[PH * PW];

__global__ void build_pair(const float* __restrict__ in) {
    int i = blockIdx.x * blockDim.x + threadIdx.x;
    if (i >= PH * PW) return;
    int py = i / PW;
    int px = i - py * PW;
    int y = py - 1;
    int x0 = px - 1;
    float l0 = 0.0f, l1 = 0.0f, h0 = 0.0f, h1 = 0.0f;
    if (y >= 0 && y < HH) {
        if (x0 >= 0) {
            l0 = in[y * WW + x0];
            l1 = in[HH * WW + y * WW + x0];
        }
        if (px < WW) {
            h0 = in[y * WW + px];
            h1 = in[HH * WW + y * WW + px];
        }
    }
    HPair p;
    p.lo = __floats2half2_rn(l0, l1);
    p.hi = __floats2half2_rn(h0, h1);
    g_ph[i] = p;
}

// Clip t so x(t)=bx-sn*t, y(t)=by+c*t stay inside (-0.999, 511.999).
__device__ __forceinline__ void clip_ray(float bx, float by, float sn, float c,
                                         int& k0, int& k1) {
    float tlo = -362.0f, thi = 362.0f;
    const float lo = -0.999f;
    const float hi = 511.999f;
    if (sn > 1e-7f) {
        float inv = __frcp_rn(sn);
        tlo = fmaxf(tlo, (bx - hi) * inv);
        thi = fminf(thi, (bx - lo) * inv);
    } else if (bx <= lo || bx >= hi) {
        thi = tlo - 1.0f;
    }
    if (c > 1e-7f) {
        float inv = __frcp_rn(c);
        tlo = fmaxf(tlo, (lo - by) * inv);
        thi = fminf(thi, (hi - by) * inv);
    } else if (c < -1e-7f) {
        float inv = __frcp_rn(c);
        tlo = fmaxf(tlo, (hi - by) * inv);
        thi = fminf(thi, (lo - by) * inv);
    } else if (by <= lo || by >= hi) {
        thi = tlo - 1.0f;
    }
    k0 = max(0, (int)ceilf(tlo + 362.0f));
    k1 = min(NT - 1, (int)floorf(thi + 362.0f));
}

#define MAGIC 8388608.0f  // 2^23

// One bilinear sample in padded coords, half2 math, accumulate into half2 pacc.
__device__ __forceinline__ void sample_h(float xp, float yp, __half2& pacc) {
    float sx = __fadd_rd(xp, MAGIC);
    float sy = __fadd_rd(yp, MAGIC);
    int ixp = __float_as_int(sx) & 0x7FFFFF;
    int iyp = __float_as_int(sy) & 0x7FFFFF;
    float wx = xp - (sx - MAGIC);
    float wy = yp - (sy - MAGIC);
    __half2 wxh = __float2half2_rn(wx);
    __half2 wyh = __float2half2_rn(wy);
    int base = iyp * PW + ixp;
    HPair r0 = g_ph[base];
    HPair r1 = g_ph[base + PW];
    __half2 a0 = __hfma2(wxh, __hsub2(r0.hi, r0.lo), r0.lo);
    __half2 a1 = __hfma2(wxh, __hsub2(r1.hi, r1.lo), r1.lo);
    __half2 val = __hfma2(wyh, __hsub2(a1, a0), a0);
    pacc = __hadd2(pacc, val);
}

__device__ __forceinline__ void ray_setup(int v, int s, float& sn, float& c,
                                          float& bxp, float& byp, int& k0, int& k1) {
    float theta = (float)v * (float)(M_PI / (double)NVIEW);
    sincosf(theta, &sn, &c);
    float sf = (float)s - 367.5f;
    float bx = fmaf(sf, c, 255.5f);
    float by = fmaf(sf, sn, 255.5f);
    clip_ray(bx, by, sn, c, k0, k1);
    bxp = bx + 1.0f;
    byp = by + 1.0f;
}

// Accumulation core: chunk of 8 samples in half2 partial sum, flushed to fp32.
template <int STRIDE>
__device__ __forceinline__ void integrate(int k0, int k1, int ti,
                                          float sn, float c, float bxp, float byp,
                                          float& accx, float& accy) {
    int k = k0 + ti;
    float tf = (float)k - 362.0f;
    while (k <= k1) {
        __half2 pacc = __float2half2_rn(0.0f);
        #pragma unroll
        for (int u = 0; u < 8; ++u) {
            if (k <= k1) {
                float xp = fmaf(tf, -sn, bxp);
                float yp = fmaf(tf, c, byp);
                sample_h(xp, yp, pacc);
            }
            k += STRIDE;
            tf += (float)STRIDE;
        }
        float2 f = __half22float2(pacc);
        accx += f.x;
        accy += f.y;
    }
}

// Kernel A: views with |cos| >= sin (v in [0,192] U [576,767]).
// Warp tile: 8 detectors x 4 t-offsets (stride 4).
__global__ void __launch_bounds__(256) radonA(float* __restrict__ out) {
    int lane = threadIdx.x & 31;
    int warp = threadIdx.x >> 5;
    int si = lane & 7;
    int ti = lane >> 3;
    int s = blockIdx.x * 64 + warp * 8 + si;
    int vy = blockIdx.y;
    int v = (vy < 193) ? vy : (vy + 383);
    if (s >= NDCT) return;  // warp-uniform

    float sn, c, bxp, byp;
    int k0, k1;
    ray_setup(v, s, sn, c, bxp, byp, k0, k1);

    float accx = 0.0f, accy = 0.0f;
    integrate<4>(k0, k1, ti, sn, c, bxp, byp, accx, accy);

    accx += __shfl_xor_sync(0xFFFFFFFFu, accx, 8);
    accy += __shfl_xor_sync(0xFFFFFFFFu, accy, 8);
    accx += __shfl_xor_sync(0xFFFFFFFFu, accx, 16);
    accy += __shfl_xor_sync(0xFFFFFFFFu, accy, 16);
    if (lane < 8) {
        out[v * NDCT + s] = accx;
        out[NVIEW * NDCT + v * NDCT + s] = accy;
    }
}

// Kernel B: views with sin > |cos| (v in [193,575]).
// Warp tile: 4 detectors x 8 t-strides (stride 8).
__global__ void __launch_bounds__(256) radonB(float* __restrict__ out) {
    int lane = threadIdx.x & 31;
    int warp = threadIdx.x >> 5;
    int si = lane & 3;
    int ti = lane >> 2;
    int s = blockIdx.x * 32 + warp * 4 + si;
    int v = 193 + blockIdx.y;

    float sn, c, bxp, byp;
    int k0, k1;
    ray_setup(v, s, sn, c, bxp, byp, k0, k1);

    float accx = 0.0f, accy = 0.0f;
    integrate<8>(k0, k1, ti, sn, c, bxp, byp, accx, accy);

    accx += __shfl_xor_sync(0xFFFFFFFFu, accx, 4);
    accy += __shfl_xor_sync(0xFFFFFFFFu, accy, 4);
    accx += __shfl_xor_sync(0xFFFFFFFFu, accx, 8);
    accy += __shfl_xor_sync(0xFFFFFFFFu, accy, 8);
    accx += __shfl_xor_sync(0xFFFFFFFFu, accx, 16);
    accy += __shfl_xor_sync(0xFFFFFFFFu, accy, 16);
    if (lane < 4) {
        out[v * NDCT + s] = accx;
        out[NVIEW * NDCT + v * NDCT + s] = accy;
    }
}

extern "C" void kernel_launch(void* const* d_in, const int* in_sizes, int n_in,
                              void* d_out, int out_size) {
    const float* in = (const float*)d_in[0];
    float* out = (float*)d_out;

    build_pair<<<(PH * PW + 255) / 256, 256>>>(in);

    dim3 gridA((NDCT + 63) / 64, 385);
    radonA<<<gridA, 256>>>(out);

    dim3 gridB(NDCT / 32, 383);
    radonB<<<gridB, 256>>>(out);
}